// round 1
// baseline (speedup 1.0000x reference)
#include <cuda_runtime.h>
#include <math_constants.h>

// Problem dims (fixed by the reference)
#define B_   4
#define T_   1024
#define H_   12
#define C_   4096
#define DK_  64
#define DV_  64
#define N_   (B_*T_)      // 4096 rows per head
#define DIM_ (H_*DK_)     // 768

// Tiling
#define TN 128            // n-tile (rows)
#define TC 128            // c-tile (codes)
#define TK 64             // full K resident
#define PSTR 132          // padded smem stride (16B aligned, conflict-mitigating)

// e2[h][c] scratch (no allocations allowed -> device global)
__device__ float g_e2[H_ * C_];

// ---------------------------------------------------------------------------
// e2 = sum_d ke[h][c][d]^2, sequential over d (mimic reference sum order)
// ---------------------------------------------------------------------------
__global__ void e2_kernel(const float* __restrict__ ke) {
    int idx = blockIdx.x * blockDim.x + threadIdx.x;   // over H*C rows
    if (idx >= H_ * C_) return;
    const float* p = ke + (size_t)idx * DK_;
    float s = 0.f;
#pragma unroll
    for (int d = 0; d < DK_; d++) s = __fmaf_rn(p[d], p[d], s);
    g_e2[idx] = s;
}

// ---------------------------------------------------------------------------
// Fused: per-head distance GEMM + argmin over C + values gather.
// Block: 256 threads (16x16), tile 128n x 128c, K=64 fully resident.
// grid = (N/TN, H)
// ---------------------------------------------------------------------------
__global__ __launch_bounds__(256, 2)
void argmin_gather_kernel(const float* __restrict__ x,
                          const float* __restrict__ ke,
                          const float* __restrict__ vals,
                          float* __restrict__ out) {
    extern __shared__ float smem[];
    float* Xs   = smem;                       // [TK][PSTR] transposed: Xs[d][r]
    float* Es   = Xs + TK * PSTR;             // [TK][PSTR] transposed: Es[d][c]
    float* x2s  = Es + TK * PSTR;             // [TN]
    float* rbv  = x2s + TN;                   // [TN][16]
    int*   rbi  = (int*)(rbv + TN * 16);      // [TN][16]
    int*   bestc = rbi + TN * 16;             // [TN]

    const int h   = blockIdx.y;
    const int nt  = blockIdx.x;
    const int tid = threadIdx.x;
    const int tx  = tid & 15;       // c-direction
    const int ty  = tid >> 4;       // n-direction

    // ---- Load X tile (once), transposed into smem --------------------------
    {
        const float* xb = x + (size_t)(nt * TN) * DIM_ + h * DK_;
#pragma unroll
        for (int i = 0; i < 8; i++) {
            int lin = tid + 256 * i;          // 0..2047 float4 slots
            int r   = lin >> 4;               // row 0..127
            int d4  = lin & 15;               // float4 index along d
            float4 v = *(const float4*)(xb + (size_t)r * DIM_ + d4 * 4);
            Xs[(d4 * 4 + 0) * PSTR + r] = v.x;
            Xs[(d4 * 4 + 1) * PSTR + r] = v.y;
            Xs[(d4 * 4 + 2) * PSTR + r] = v.z;
            Xs[(d4 * 4 + 3) * PSTR + r] = v.w;
        }
    }
    __syncthreads();

    // ---- x2 per row (sequential over d, mimic reference) -------------------
    if (tid < TN) {
        float s = 0.f;
#pragma unroll
        for (int d = 0; d < TK; d++) {
            float v = Xs[d * PSTR + tid];
            s = __fmaf_rn(v, v, s);
        }
        x2s[tid] = s;
    }

    // ---- Running argmin state ---------------------------------------------
    float bestv[8];
    int   besti[8];
#pragma unroll
    for (int i = 0; i < 8; i++) { bestv[i] = CUDART_INF_F; besti[i] = 0; }

    const float* keh = ke + (size_t)h * C_ * DK_;
    const float* e2h = g_e2 + h * C_;

    for (int ct = 0; ct < C_ / TC; ct++) {
        __syncthreads();   // protect Es (and x2s on first iter)

        // Load E tile transposed
        {
            const float* eb = keh + (size_t)(ct * TC) * DK_;
#pragma unroll
            for (int i = 0; i < 8; i++) {
                int lin = tid + 256 * i;
                int r   = lin >> 4;
                int d4  = lin & 15;
                float4 v = *(const float4*)(eb + (size_t)r * DK_ + d4 * 4);
                Es[(d4 * 4 + 0) * PSTR + r] = v.x;
                Es[(d4 * 4 + 1) * PSTR + r] = v.y;
                Es[(d4 * 4 + 2) * PSTR + r] = v.z;
                Es[(d4 * 4 + 3) * PSTR + r] = v.w;
            }
        }
        __syncthreads();

        // ---- 128x128x64 micro-GEMM ----------------------------------------
        float acc[8][8];
#pragma unroll
        for (int i = 0; i < 8; i++)
#pragma unroll
            for (int j = 0; j < 8; j++) acc[i][j] = 0.f;

#pragma unroll 8
        for (int k = 0; k < TK; k++) {
            float a[8], b[8];
            float4 a0 = *(const float4*)&Xs[k * PSTR + ty * 8];
            float4 a1 = *(const float4*)&Xs[k * PSTR + ty * 8 + 4];
            float4 b0 = *(const float4*)&Es[k * PSTR + tx * 8];
            float4 b1 = *(const float4*)&Es[k * PSTR + tx * 8 + 4];
            a[0]=a0.x; a[1]=a0.y; a[2]=a0.z; a[3]=a0.w;
            a[4]=a1.x; a[5]=a1.y; a[6]=a1.z; a[7]=a1.w;
            b[0]=b0.x; b[1]=b0.y; b[2]=b0.z; b[3]=b0.w;
            b[4]=b1.x; b[5]=b1.y; b[6]=b1.z; b[7]=b1.w;
#pragma unroll
            for (int i = 0; i < 8; i++)
#pragma unroll
                for (int j = 0; j < 8; j++)
                    acc[i][j] = __fmaf_rn(a[i], b[j], acc[i][j]);
        }

        // ---- Epilogue: d2 = fl(fl(x2 - 2*dot) + e2), running argmin -------
        float e2v[8];
#pragma unroll
        for (int j = 0; j < 8; j++) e2v[j] = e2h[ct * TC + tx * 8 + j];

#pragma unroll
        for (int i = 0; i < 8; i++) {
            float x2v = x2s[ty * 8 + i];
#pragma unroll
            for (int j = 0; j < 8; j++) {
                // fl(x2 - 2*dot): 2*dot is exact, so single fma == reference's
                // two-step rounding. Then one separate rounded add of e2.
                float t = __fmaf_rn(-2.0f, acc[i][j], x2v);
                float s = __fadd_rn(t, e2v[j]);
                int   c = ct * TC + tx * 8 + j;
                // strict < keeps the earliest (smallest c) on exact ties,
                // since scan order is ascending in c within this thread.
                if (s < bestv[i]) { bestv[i] = s; besti[i] = c; }
            }
        }
    }

    // ---- Cross-thread argmin reduce (lexicographic: val, then index) -------
    __syncthreads();
#pragma unroll
    for (int i = 0; i < 8; i++) {
        rbv[(ty * 8 + i) * 16 + tx] = bestv[i];
        rbi[(ty * 8 + i) * 16 + tx] = besti[i];
    }
    __syncthreads();
    if (tid < TN) {
        float bv = rbv[tid * 16 + 0];
        int   bi = rbi[tid * 16 + 0];
#pragma unroll
        for (int t = 1; t < 16; t++) {
            float v = rbv[tid * 16 + t];
            int   c = rbi[tid * 16 + t];
            if (v < bv || (v == bv && c < bi)) { bv = v; bi = c; }
        }
        bestc[tid] = bi;
    }
    __syncthreads();

    // ---- Gather values into out[b,t,h*DV + v] ------------------------------
    const float* vh = vals + (size_t)h * C_ * DV_;
    float* ob = out + (size_t)(nt * TN) * DIM_ + h * DV_;
#pragma unroll
    for (int i = 0; i < 8; i++) {
        int lin = tid + 256 * i;          // 0..2047 float4 slots
        int r   = lin >> 4;
        int v4  = lin & 15;
        float4 v = *(const float4*)(vh + (size_t)bestc[r] * DV_ + v4 * 4);
        *(float4*)(ob + (size_t)r * DIM_ + v4 * 4) = v;
    }
}

// ---------------------------------------------------------------------------
extern "C" void kernel_launch(void* const* d_in, const int* in_sizes, int n_in,
                              void* d_out, int out_size) {
    const float* x    = (const float*)d_in[0];   // [4,1024,768]
    // d_in[1] = mask (unused by reference)
    const float* ke   = (const float*)d_in[2];   // [12,4096,64]
    const float* vals = (const float*)d_in[3];   // [12,4096,64]
    // d_in[4] = key_optim (unused)
    float* out = (float*)d_out;                  // [4,1024,768] fp32

    // Dynamic smem: Xs + Es + x2s + rbv + rbi + bestc
    const int smem_bytes =
        (TK * PSTR + TK * PSTR + TN + TN * 16 + TN * 16 + TN) * (int)sizeof(float);
    cudaFuncSetAttribute(argmin_gather_kernel,
                         cudaFuncAttributeMaxDynamicSharedMemorySize, smem_bytes);

    e2_kernel<<<(H_ * C_ + 255) / 256, 256>>>(ke);

    dim3 grid(N_ / TN, H_);
    argmin_gather_kernel<<<grid, 256, smem_bytes>>>(x, ke, vals, out);
}

// round 2
// speedup vs baseline: 1.0711x; 1.0711x over previous
#include <cuda_runtime.h>
#include <math_constants.h>

// Problem dims (fixed by the reference)
#define B_   4
#define T_   1024
#define H_   12
#define C_   4096
#define DK_  64
#define DV_  64
#define N_   (B_*T_)      // 4096 rows per head
#define DIM_ (H_*DK_)     // 768

// Tiling
#define TN 128            // n-tile (rows)
#define TC 128            // c-tile (codes)
#define TK 64             // full K resident
#define PSTR 132          // padded smem stride (16B aligned: 132*4=528)

__device__ float g_e2[H_ * C_];

// Pack two identical fp32 into a 64-bit pair
__device__ __forceinline__ unsigned long long dup_f32x2(float v) {
    unsigned long long r;
    unsigned int b = __float_as_uint(v);
    asm("mov.b64 %0, {%1, %2};" : "=l"(r) : "r"(b), "r"(b));
    return r;
}

__device__ __forceinline__ void unpack_f32x2(unsigned long long p, float& lo, float& hi) {
    unsigned int a, b;
    asm("mov.b64 {%0, %1}, %2;" : "=r"(a), "=r"(b) : "l"(p));
    lo = __uint_as_float(a);
    hi = __uint_as_float(b);
}

// Packed fp32x2 FMA: d = a*b + c per 32-bit lane, round-to-nearest.
// Bitwise identical to two scalar FFMAs.
__device__ __forceinline__ void ffma2(unsigned long long& d,
                                      unsigned long long a,
                                      unsigned long long b) {
    asm("fma.rn.f32x2 %0, %1, %2, %3;" : "=l"(d) : "l"(a), "l"(b), "l"(d));
}

// ---------------------------------------------------------------------------
// e2 = sum_d ke[h][c][d]^2, sequential over d (mimic reference sum order)
// ---------------------------------------------------------------------------
__global__ void e2_kernel(const float* __restrict__ ke) {
    int idx = blockIdx.x * blockDim.x + threadIdx.x;   // over H*C rows
    if (idx >= H_ * C_) return;
    const float* p = ke + (size_t)idx * DK_;
    float s = 0.f;
#pragma unroll
    for (int d = 0; d < DK_; d++) s = __fmaf_rn(p[d], p[d], s);
    g_e2[idx] = s;
}

// ---------------------------------------------------------------------------
// Fused: per-head distance GEMM (FFMA2) + argmin over C + values gather.
// Block: 256 threads (16x16), tile 128n x 128c, K=64 fully resident.
// grid = (N/TN, H)
// ---------------------------------------------------------------------------
__global__ __launch_bounds__(256, 2)
void argmin_gather_kernel(const float* __restrict__ x,
                          const float* __restrict__ ke,
                          const float* __restrict__ vals,
                          float* __restrict__ out) {
    extern __shared__ float smem[];
    float* Xs   = smem;                       // [TK][PSTR] transposed: Xs[d][r]
    float* Es   = Xs + TK * PSTR;             // [TK][PSTR] transposed: Es[d][c]
    float* x2s  = Es + TK * PSTR;             // [TN]
    float* rbv  = x2s + TN;                   // [TN][16]
    int*   rbi  = (int*)(rbv + TN * 16);      // [TN][16]
    int*   bestc = rbi + TN * 16;             // [TN]

    const int h   = blockIdx.y;
    const int nt  = blockIdx.x;
    const int tid = threadIdx.x;
    const int tx  = tid & 15;       // c-direction
    const int ty  = tid >> 4;       // n-direction

    // ---- Load X tile (once), transposed into smem --------------------------
    {
        const float* xb = x + (size_t)(nt * TN) * DIM_ + h * DK_;
#pragma unroll
        for (int i = 0; i < 8; i++) {
            int lin = tid + 256 * i;          // 0..2047 float4 slots
            int r   = lin >> 4;               // row 0..127
            int d4  = lin & 15;               // float4 index along d
            float4 v = *(const float4*)(xb + (size_t)r * DIM_ + d4 * 4);
            Xs[(d4 * 4 + 0) * PSTR + r] = v.x;
            Xs[(d4 * 4 + 1) * PSTR + r] = v.y;
            Xs[(d4 * 4 + 2) * PSTR + r] = v.z;
            Xs[(d4 * 4 + 3) * PSTR + r] = v.w;
        }
    }
    __syncthreads();

    // ---- x2 per row (sequential over d, mimic reference) -------------------
    if (tid < TN) {
        float s = 0.f;
#pragma unroll
        for (int d = 0; d < TK; d++) {
            float v = Xs[d * PSTR + tid];
            s = __fmaf_rn(v, v, s);
        }
        x2s[tid] = s;
    }

    // ---- Running argmin state ---------------------------------------------
    float bestv[8];
    int   besti[8];
#pragma unroll
    for (int i = 0; i < 8; i++) { bestv[i] = CUDART_INF_F; besti[i] = 0; }

    const float* keh = ke + (size_t)h * C_ * DK_;
    const float* e2h = g_e2 + h * C_;

    for (int ct = 0; ct < C_ / TC; ct++) {
        __syncthreads();   // protect Es (and x2s on first iter)

        // Load E tile transposed
        {
            const float* eb = keh + (size_t)(ct * TC) * DK_;
#pragma unroll
            for (int i = 0; i < 8; i++) {
                int lin = tid + 256 * i;
                int r   = lin >> 4;
                int d4  = lin & 15;
                float4 v = *(const float4*)(eb + (size_t)r * DK_ + d4 * 4);
                Es[(d4 * 4 + 0) * PSTR + r] = v.x;
                Es[(d4 * 4 + 1) * PSTR + r] = v.y;
                Es[(d4 * 4 + 2) * PSTR + r] = v.z;
                Es[(d4 * 4 + 3) * PSTR + r] = v.w;
            }
        }
        __syncthreads();

        // ---- 128x128x64 micro-GEMM via packed fp32x2 FMA ------------------
        // acc2[i2][j]: lanes = rows (ty*8 + 2*i2, ty*8 + 2*i2 + 1), col j.
        unsigned long long acc2[4][8];
#pragma unroll
        for (int i = 0; i < 4; i++)
#pragma unroll
            for (int j = 0; j < 8; j++) acc2[i][j] = 0ull;

#pragma unroll 4
        for (int k = 0; k < TK; k++) {
            // Row pairs come packed for free from 16B smem loads.
            ulonglong2 A01 = *(const ulonglong2*)&Xs[k * PSTR + ty * 8];
            ulonglong2 A23 = *(const ulonglong2*)&Xs[k * PSTR + ty * 8 + 4];
            unsigned long long ap[4] = { A01.x, A01.y, A23.x, A23.y };

            float4 b0 = *(const float4*)&Es[k * PSTR + tx * 8];
            float4 b1 = *(const float4*)&Es[k * PSTR + tx * 8 + 4];
            unsigned long long bd[8];
            bd[0] = dup_f32x2(b0.x); bd[1] = dup_f32x2(b0.y);
            bd[2] = dup_f32x2(b0.z); bd[3] = dup_f32x2(b0.w);
            bd[4] = dup_f32x2(b1.x); bd[5] = dup_f32x2(b1.y);
            bd[6] = dup_f32x2(b1.z); bd[7] = dup_f32x2(b1.w);

#pragma unroll
            for (int i = 0; i < 4; i++)
#pragma unroll
                for (int j = 0; j < 8; j++)
                    ffma2(acc2[i][j], ap[i], bd[j]);
        }

        // ---- Epilogue: d2 = fl(fl(x2 - 2*dot) + e2), running argmin -------
        float e2v[8];
#pragma unroll
        for (int j = 0; j < 8; j++) e2v[j] = e2h[ct * TC + tx * 8 + j];

#pragma unroll
        for (int i2 = 0; i2 < 4; i2++) {
            float x2lo = x2s[ty * 8 + 2 * i2];
            float x2hi = x2s[ty * 8 + 2 * i2 + 1];
#pragma unroll
            for (int j = 0; j < 8; j++) {
                float dlo, dhi;
                unpack_f32x2(acc2[i2][j], dlo, dhi);
                int c = ct * TC + tx * 8 + j;
                // fl(x2 - 2*dot): 2*dot exact, single fma == reference's
                // two-step rounding; then one separate rounded add of e2.
                float tlo = __fmaf_rn(-2.0f, dlo, x2lo);
                float slo = __fadd_rn(tlo, e2v[j]);
                if (slo < bestv[2 * i2]) { bestv[2 * i2] = slo; besti[2 * i2] = c; }
                float thi = __fmaf_rn(-2.0f, dhi, x2hi);
                float shi = __fadd_rn(thi, e2v[j]);
                if (shi < bestv[2 * i2 + 1]) { bestv[2 * i2 + 1] = shi; besti[2 * i2 + 1] = c; }
            }
        }
    }

    // ---- Cross-thread argmin reduce (lexicographic: val, then index) -------
    __syncthreads();
#pragma unroll
    for (int i = 0; i < 8; i++) {
        rbv[(ty * 8 + i) * 16 + tx] = bestv[i];
        rbi[(ty * 8 + i) * 16 + tx] = besti[i];
    }
    __syncthreads();
    if (tid < TN) {
        float bv = rbv[tid * 16 + 0];
        int   bi = rbi[tid * 16 + 0];
#pragma unroll
        for (int t = 1; t < 16; t++) {
            float v = rbv[tid * 16 + t];
            int   c = rbi[tid * 16 + t];
            if (v < bv || (v == bv && c < bi)) { bv = v; bi = c; }
        }
        bestc[tid] = bi;
    }
    __syncthreads();

    // ---- Gather values into out[b,t,h*DV + v] ------------------------------
    const float* vh = vals + (size_t)h * C_ * DV_;
    float* ob = out + (size_t)(nt * TN) * DIM_ + h * DV_;
#pragma unroll
    for (int i = 0; i < 8; i++) {
        int lin = tid + 256 * i;          // 0..2047 float4 slots
        int r   = lin >> 4;
        int v4  = lin & 15;
        float4 v = *(const float4*)(vh + (size_t)bestc[r] * DV_ + v4 * 4);
        *(float4*)(ob + (size_t)r * DIM_ + v4 * 4) = v;
    }
}

// ---------------------------------------------------------------------------
extern "C" void kernel_launch(void* const* d_in, const int* in_sizes, int n_in,
                              void* d_out, int out_size) {
    const float* x    = (const float*)d_in[0];   // [4,1024,768]
    // d_in[1] = mask (unused by reference)
    const float* ke   = (const float*)d_in[2];   // [12,4096,64]
    const float* vals = (const float*)d_in[3];   // [12,4096,64]
    // d_in[4] = key_optim (unused)
    float* out = (float*)d_out;                  // [4,1024,768] fp32

    const int smem_bytes =
        (TK * PSTR + TK * PSTR + TN + TN * 16 + TN * 16 + TN) * (int)sizeof(float);
    cudaFuncSetAttribute(argmin_gather_kernel,
                         cudaFuncAttributeMaxDynamicSharedMemorySize, smem_bytes);

    e2_kernel<<<(H_ * C_ + 255) / 256, 256>>>(ke);

    dim3 grid(N_ / TN, H_);
    argmin_gather_kernel<<<grid, 256, smem_bytes>>>(x, ke, vals, out);
}